// round 3
// baseline (speedup 1.0000x reference)
#include <cuda_runtime.h>
#include <cstdint>

#define DD 128
#define KK 32
#define NTHREADS 512
#define NBLOCKS 444

// ---- shared memory layout (float offsets) ----
// s_top : per-dim packed top knots {x4,x8,x12,x16, x20,x24,x28,pad},
//         row stride 12 floats (48B) -> LDS.128 conflict-free
// s_xpos: [33][128] knots, bank = dim mod 32 = lane -> conflict-free LDS.32
// s_ys  : [33][128] float2 {ypos, slope}           -> conflict-free LDS.64
// s_ib  : [32][128] 1/bin_width (exact div)
#define TOP_OFF  0
#define XPOS_OFF (128 * 12)
#define YS_OFF   (XPOS_OFF + 33 * DD)
#define IB_OFF   (YS_OFF + 2 * 33 * DD)
#define SMEM_FLOATS (IB_OFF + 32 * DD)

__global__ void __launch_bounds__(NTHREADS, 3)
rqs_kernel(const float* __restrict__ x,
           const float* __restrict__ sp,
           float* __restrict__ y_out,
           float* __restrict__ ld_out,
           int n_rows)
{
    extern __shared__ float sm[];
    float*  s_top  = sm + TOP_OFF;
    float*  s_xpos = sm + XPOS_OFF;
    float2* s_ys   = (float2*)(sm + YS_OFF);
    float*  s_ib   = sm + IB_OFF;

    const int tid = threadIdx.x;
    const float TOTAL_M = 10.0f - KK * 1e-4f;

    // ---- per-block table build (redundant across blocks, trivially cheap) ----
    if (tid < DD) {
        // widths -> x_pos, inv bin width, top-knot table
        const int d = tid;
        const float* uw = sp + d * (3 * KK + 1);
        float m = -1e30f;
        #pragma unroll 1
        for (int k = 0; k < KK; k++) m = fmaxf(m, uw[k]);
        float s = 0.f;
        #pragma unroll 1
        for (int k = 0; k < KK; k++) s += __expf(uw[k] - m);
        float scale = TOTAL_M / s;
        float run = -5.0f;
        s_xpos[d] = run;
        #pragma unroll 1
        for (int k = 0; k < KK; k++) {
            float w = __expf(uw[k] - m) * scale + 1e-4f;
            float nxt = run + w;
            s_xpos[(k + 1) * DD + d] = nxt;
            s_ib[k * DD + d] = 1.0f / (nxt - run);
            int kp = k + 1;
            if ((kp & 3) == 0 && kp <= 28)
                s_top[d * 12 + (kp >> 2) - 1] = nxt;
            run = nxt;
        }
    } else if (tid < 2 * DD) {
        // heights -> y_pos (.x of float2), slopes (.y of float2)
        const int d = tid - DD;
        const float* uh = sp + d * (3 * KK + 1) + KK;
        const float* us = sp + d * (3 * KK + 1) + 2 * KK;
        float m = -1e30f;
        #pragma unroll 1
        for (int k = 0; k < KK; k++) m = fmaxf(m, uh[k]);
        float s = 0.f;
        #pragma unroll 1
        for (int k = 0; k < KK; k++) s += __expf(uh[k] - m);
        float scale = TOTAL_M / s;
        float run = -5.0f;
        s_ys[d].x = run;
        #pragma unroll 1
        for (int k = 0; k < KK; k++) {
            float h = __expf(uh[k] - m) * scale + 1e-4f;
            run += h;
            s_ys[(k + 1) * DD + d].x = run;
        }
        // slopes = softplus(us + offset) + min_knot_slope
        const float OFFS = 0.5411666430f;  // log(expm1(1 - 1e-4))
        #pragma unroll 1
        for (int k = 0; k <= KK; k++) {
            float v = us[k] + OFFS;
            float spv = fmaxf(v, 0.f) + __logf(1.f + __expf(-fabsf(v)));
            s_ys[k * DD + d].y = spv + 1e-4f;
        }
    }
    __syncthreads();

    // ---- main loop: one warp per row, lane handles dims lane+32j ----
    const int lane = tid & 31;
    const int warp = (blockIdx.x * NTHREADS + tid) >> 5;
    const int nwarps = gridDim.x * (NTHREADS >> 5);
    const float LN2 = 0.69314718055994531f;

    for (int row = warp; row < n_rows; row += nwarps) {
        const float* xr = x + (size_t)row * DD;
        float prod = 1.0f;
        float yv[4];

        #pragma unroll
        for (int j = 0; j < 4; j++) {
            const int d = lane + 32 * j;
            float xv = xr[d];

            // stage A: top 3 binary levels from packed registers (1 chain level)
            float4 t0 = *(const float4*)(s_top + d * 12);      // x4 x8 x12 x16
            float4 t1 = *(const float4*)(s_top + d * 12 + 4);  // x20 x24 x28 -
            bool c1 = xv >= t0.w;                       // vs x16
            float m1 = c1 ? t1.y : t0.y;                // x24 : x8
            bool c2 = xv >= m1;
            float m2 = c1 ? (c2 ? t1.z : t1.x)          // x28 : x20
                          : (c2 ? t0.z : t0.x);         // x12 : x4
            bool c3 = xv >= m2;
            int b = (c1 ? 16 : 0) + (c2 ? 8 : 0) + (c3 ? 4 : 0);

            // stage B: last 2 levels as a count over 3 parallel loads
            const float* xb = s_xpos + b * DD + d;
            float k1 = xb[1 * DD];
            float k2 = xb[2 * DD];
            float k3 = xb[3 * DD];
            int idx = b + (xv >= k1) + (xv >= k2) + (xv >= k3);
            const int o = idx * DD + d;

            // fetch level: all parallel
            float  x0  = s_xpos[o];
            float2 ys0 = s_ys[o];
            float2 ys1 = s_ys[o + DD];
            float  ib  = s_ib[o];

            float y0 = ys0.x, s0 = ys0.y;
            float y1 = ys1.x, s1 = ys1.y;

            float zr   = (xv - x0) * ib;
            float z    = fminf(fmaxf(zr, 0.f), 1.f);
            float bh   = y1 - y0;
            float bs   = bh * ib;
            float sqz  = z * z;
            float z1mz = z - sqz;
            float omz  = 1.f - z;
            float sq1  = omz * omz;

            float st  = (s0 + s1) - 2.f * bs;
            float den = fmaf(st, z1mz, bs);
            float num = bh * fmaf(s0, z1mz, bs * sqz);

            float r;
            asm("rcp.approx.f32 %0, %1;" : "=f"(r) : "f"(den));
            float yy = fmaf(num, r, y0);

            // derivative = bs^2 * arg / den^2 ; fold bs^2 via t = bs * (1/den)
            float arg = fmaf(s1, sqz, fmaf(s0, sq1, (bs + bs) * z1mz));
            float t   = bs * r;
            float deriv = (t * t) * arg;

            // out-of-range tails (P ~ 6e-7): linear extrapolation, edge slopes
            if (zr != z) {
                if (zr < 0.f) {
                    yy = fmaf(xv - x0, s0, y0);
                    deriv = s0;
                } else {
                    float x1 = s_xpos[o + DD];
                    yy = fmaf(xv - x1, s1, y1);
                    deriv = s1;
                }
            }
            prod *= deriv;
            yv[j] = yy;
        }

        float* yr = y_out + (size_t)row * DD;
        #pragma unroll
        for (int j = 0; j < 4; j++) yr[lane + 32 * j] = yv[j];

        // one LG2 per 4 elements, then warp-sum; scale by ln2 once per row
        float ls = __log2f(prod);
        #pragma unroll
        for (int off = 16; off; off >>= 1)
            ls += __shfl_xor_sync(0xffffffffu, ls, off);
        if (lane == 0) ld_out[row] = ls * LN2;
    }
}

extern "C" void kernel_launch(void* const* d_in, const int* in_sizes, int n_in,
                              void* d_out, int out_size)
{
    const float* x  = (const float*)d_in[0];
    const float* sp = (const float*)d_in[1];
    const int n_rows = in_sizes[0] / DD;

    float* y_out  = (float*)d_out;
    float* ld_out = (float*)d_out + (size_t)n_rows * DD;

    const size_t smem = SMEM_FLOATS * sizeof(float);
    cudaFuncSetAttribute(rqs_kernel, cudaFuncAttributeMaxDynamicSharedMemorySize,
                         (int)smem);
    rqs_kernel<<<NBLOCKS, NTHREADS, smem>>>(x, sp, y_out, ld_out, n_rows);
}